// round 2
// baseline (speedup 1.0000x reference)
#include <cuda_runtime.h>
#include <cstdint>

// MaxUnpooling2D: updates [16,64,64,256] f32, mask [16,64,64,256] i32 (flat idx
// into [16,128,128,256]), out [16,128,128,256] f32.
//
// Each pooled cell (b,h,w,c) targets exactly one position in its private 2x2
// window -> no duplicates -> plain stores; zero-fill is fused (each thread
// writes all 4 window positions for its 4 channels).
//
// R2 changes vs R1 (59.1us kernel, DRAM 71.7%):
//  - 2 float4-groups per thread, block-strided (+256) so every LDG/STG is a
//    fully coalesced 512B warp access; all 4 loads issued before any store
//    (double the front-batched MLP).
//  - __ldcs / __stcs streaming hints: zero reuse, keep L2 evict-first.

namespace {
constexpr int B  = 16;
constexpr int H  = 64;
constexpr int W  = 64;
constexpr int C  = 256;
constexpr int ROW   = 2 * W * C;       // 32768  (dy=1 stride in out)
constexpr int COLS  = C;               // 256    (dx=1 stride in out)
constexpr int IMG   = 2 * H * ROW;     // 4194304 (batch stride in out)
constexpr int NGROUPS = B * H * W * (C / 4);   // 4,194,304 float4 groups
constexpr int THREADS = 256;
constexpr int GROUPS_PER_BLOCK = 2 * THREADS;  // 512
constexpr int BLOCKS = NGROUPS / GROUPS_PER_BLOCK;  // 8192
}

__device__ __forceinline__ int origin_of(int t)
{
    // t = ((b*H + h)*W + w)*(C/4) + c4  ->  flat out index of window origin
    int c4 = t & 63;
    int w  = (t >> 6)  & 63;
    int h  = (t >> 12) & 63;
    int b  = t >> 18;
    return b * IMG + (h << 1) * ROW + (w << 1) * COLS + (c4 << 2);
}

__device__ __forceinline__ void scatter_group(float* __restrict__ out,
                                              int o00, float4 v, int4 m)
{
    int d0 = m.x - o00;
    int d1 = m.y - o00 - 1;
    int d2 = m.z - o00 - 2;
    int d3 = m.w - o00 - 3;

    float4 r00 = make_float4(d0 == 0          ? v.x : 0.f,
                             d1 == 0          ? v.y : 0.f,
                             d2 == 0          ? v.z : 0.f,
                             d3 == 0          ? v.w : 0.f);
    float4 r01 = make_float4(d0 == COLS       ? v.x : 0.f,
                             d1 == COLS       ? v.y : 0.f,
                             d2 == COLS       ? v.z : 0.f,
                             d3 == COLS       ? v.w : 0.f);
    float4 r10 = make_float4(d0 == ROW        ? v.x : 0.f,
                             d1 == ROW        ? v.y : 0.f,
                             d2 == ROW        ? v.z : 0.f,
                             d3 == ROW        ? v.w : 0.f);
    float4 r11 = make_float4(d0 == ROW + COLS ? v.x : 0.f,
                             d1 == ROW + COLS ? v.y : 0.f,
                             d2 == ROW + COLS ? v.z : 0.f,
                             d3 == ROW + COLS ? v.w : 0.f);

    __stcs(reinterpret_cast<float4*>(out + o00),              r00);
    __stcs(reinterpret_cast<float4*>(out + o00 + COLS),       r01);
    __stcs(reinterpret_cast<float4*>(out + o00 + ROW),        r10);
    __stcs(reinterpret_cast<float4*>(out + o00 + ROW + COLS), r11);
}

__global__ void __launch_bounds__(THREADS, 8)
max_unpool_kernel(const float4* __restrict__ upd,
                  const int4*  __restrict__ mask,
                  float*       __restrict__ out)
{
    int g0 = blockIdx.x * GROUPS_PER_BLOCK + threadIdx.x;
    int g1 = g0 + THREADS;

    // Front-batch all 4 independent 16B loads (MLP), streaming-hinted.
    float4 v0 = __ldcs(upd  + g0);
    float4 v1 = __ldcs(upd  + g1);
    int4   m0 = __ldcs(mask + g0);
    int4   m1 = __ldcs(mask + g1);

    scatter_group(out, origin_of(g0), v0, m0);
    scatter_group(out, origin_of(g1), v1, m1);
}

extern "C" void kernel_launch(void* const* d_in, const int* in_sizes, int n_in,
                              void* d_out, int out_size)
{
    const float4* upd  = reinterpret_cast<const float4*>(d_in[0]);
    const int4*   mask = reinterpret_cast<const int4*>(d_in[1]);
    float*        out  = reinterpret_cast<float*>(d_out);

    max_unpool_kernel<<<BLOCKS, THREADS>>>(upd, mask, out);
}